// round 13
// baseline (speedup 1.0000x reference)
#include <cuda_runtime.h>
#include <math.h>

// Problem dims (fixed by the reference)
namespace {
constexpr int B = 4, C = 256, T = 4096;
constexpr float EPS = 1e-5f;
constexpr float NEG = -1e8f;
}

// ---------------------------------------------------------------------------
// Scratch buffers (static __device__ arrays — allocation-free per harness rules)
// ---------------------------------------------------------------------------
__device__ float g_ln  [(size_t)B * C * T];
__device__ float g_h1  [(size_t)B * C * T];
__device__ float g_qb  [(size_t)B * C * T];
__device__ float g_kb  [(size_t)B * C * T];
__device__ float g_vb  [(size_t)B * C * T];
__device__ float g_attn[(size_t)B * C * T];

// ---------------------------------------------------------------------------
// Kernel 1: masked LayerNorm over channel dim.
//   h = x * m ; ln[b,c,t] = (h - mu_t) * rsqrt(var_t + eps) * gamma[c] + beta[c]
// Layout [B,C,T]; one thread per (b,t); loops over c are coalesced across t.
// ---------------------------------------------------------------------------
__global__ void ln_kernel(const float* __restrict__ x,
                          const float* __restrict__ mask,
                          const float* __restrict__ gamma,
                          const float* __restrict__ beta) {
    const int b = blockIdx.y;
    const int t = blockIdx.x * blockDim.x + threadIdx.x;
    const float m = mask[(size_t)b * T + t];
    const float* xp = x + (size_t)b * C * T + t;

    float sum = 0.f, sq = 0.f;
#pragma unroll 8
    for (int c = 0; c < C; c++) {
        float v = __ldg(&xp[(size_t)c * T]) * m;
        sum += v;
        sq  += v * v;
    }
    const float mu  = sum * (1.0f / C);
    float var = sq * (1.0f / C) - mu * mu;
    var = fmaxf(var, 0.0f);
    const float rs = rsqrtf(var + EPS);

    float* op = g_ln + (size_t)b * C * T + t;
#pragma unroll 8
    for (int c = 0; c < C; c++) {
        float v = __ldg(&xp[(size_t)c * T]) * m;
        op[(size_t)c * T] = (v - mu) * rs * __ldg(&gamma[c]) + __ldg(&beta[c]);
    }
}

// ---------------------------------------------------------------------------
// Kernel 2: projection GEMM.
//   out[b,o,t] = (sum_c W[o,c] * in[b,c,t] + bias[o]) * mask[b,t]
//   if resid != null: out = (resid + out) * mask   (final Wo + residual path)
// Tiles: 64(M) x 64(N) x 16(K), 256 threads, 4x4 register micro-tile.
// ---------------------------------------------------------------------------
__global__ __launch_bounds__(256) void gemm_kernel(
    const float* __restrict__ W,      // [C, C] row-major (o major, c contiguous)
    const float* __restrict__ bias,   // [C]
    const float* __restrict__ in,     // [B, C, T]
    const float* __restrict__ mask,   // [B, T]
    const float* __restrict__ resid,  // [B, C, T] or nullptr
    float* __restrict__ out)          // [B, C, T]
{
    __shared__ __align__(16) float As[16][68];  // As[k][m]
    __shared__ __align__(16) float Bs[16][68];  // Bs[k][n]

    const int b  = blockIdx.z;
    const int m0 = blockIdx.y * 64;
    const int n0 = blockIdx.x * 64;
    const int tid = threadIdx.x;
    const int tx = tid & 15, ty = tid >> 4;

    const float* inb = in + (size_t)b * C * T;

    float acc[4][4] = {};

    const int arow = tid >> 2;          // 0..63
    const int akc  = (tid & 3) * 4;     // 0,4,8,12
    const int brow = tid >> 4;          // 0..15
    const int bcol = (tid & 15) * 4;    // 0..60

    for (int k0 = 0; k0 < C; k0 += 16) {
        // prefetch to registers
        float4 a4 = *(const float4*)&W[(size_t)(m0 + arow) * C + k0 + akc];
        float4 b4 = *(const float4*)&inb[(size_t)(k0 + brow) * T + n0 + bcol];
        __syncthreads();  // previous tile fully consumed
        As[akc + 0][arow] = a4.x;
        As[akc + 1][arow] = a4.y;
        As[akc + 2][arow] = a4.z;
        As[akc + 3][arow] = a4.w;
        *(float4*)&Bs[brow][bcol] = b4;
        __syncthreads();
#pragma unroll
        for (int k = 0; k < 16; k++) {
            float4 av4 = *(const float4*)&As[k][ty * 4];
            float4 bv4 = *(const float4*)&Bs[k][tx * 4];
            float av[4] = {av4.x, av4.y, av4.z, av4.w};
            float bv[4] = {bv4.x, bv4.y, bv4.z, bv4.w};
#pragma unroll
            for (int i = 0; i < 4; i++)
#pragma unroll
                for (int j = 0; j < 4; j++)
                    acc[i][j] = fmaf(av[i], bv[j], acc[i][j]);
        }
    }

    // epilogue
    const int tglob = n0 + tx * 4;
    float4 mk4 = *(const float4*)&mask[(size_t)b * T + tglob];
    float mk[4] = {mk4.x, mk4.y, mk4.z, mk4.w};

#pragma unroll
    for (int i = 0; i < 4; i++) {
        const int o = m0 + ty * 4 + i;
        const float bo = __ldg(&bias[o]);
        const size_t base = ((size_t)b * C + o) * T + tglob;
        float vals[4];
#pragma unroll
        for (int j = 0; j < 4; j++) vals[j] = (acc[i][j] + bo) * mk[j];
        if (resid != nullptr) {
            float4 x4 = *(const float4*)&resid[base];
            float xr[4] = {x4.x, x4.y, x4.z, x4.w};
#pragma unroll
            for (int j = 0; j < 4; j++) vals[j] = (xr[j] + vals[j]) * mk[j];
        }
        float4 r = make_float4(vals[0], vals[1], vals[2], vals[3]);
        *(float4*)&out[base] = r;
    }
}

// ---------------------------------------------------------------------------
// Kernel 3: flash attention (fp32 SIMT).
//   scores[t,s] = (sum_c q[c,t]*k[c,s]) * C^-0.5 + (1-m[s])*NEG
//   w = softmax_s(scores) ; attn[c,t] = sum_s v[c,s]*w[t,s]
// Block = 64 queries x full key loop (tiles of 64). 256 threads (16x16).
// Q tile (256x64 fp32 = 64KB) resident in smem. Online softmax.
// ---------------------------------------------------------------------------
struct AttnSmem {
    float Qs[256][64];   // Qs[c][q]           65536 B
    float Ks[32][64];    // Ks[c_local][s]      8192 B
    float Ps[64][68];    // Ps[q][s] (padded)  17408 B (reused for output transpose)
    float Vs[64][68];    // Vs[s][d] (padded)  17408 B
    float bias_s[64];    //                      256 B
};                       // total 108800 B

__global__ __launch_bounds__(256, 2) void attn_kernel(const float* __restrict__ mask) {
    extern __shared__ __align__(16) char smraw[];
    AttnSmem* sm = reinterpret_cast<AttnSmem*>(smraw);

    const int b  = blockIdx.y;
    const int q0 = blockIdx.x * 64;
    const int tid = threadIdx.x;
    const int tx = tid & 15, ty = tid >> 4;

    const float* Qb = g_qb + (size_t)b * C * T;
    const float* Kb = g_kb + (size_t)b * C * T;
    const float* Vb = g_vb + (size_t)b * C * T;
    const float* mb = mask + (size_t)b * T;

    // Load Q tile: Qs[c][q] = Q[c][q0+q]
    {
        const int col = (tid & 15) * 4;
        for (int c = tid >> 4; c < C; c += 16)
            *(float4*)&sm->Qs[c][col] = *(const float4*)&Qb[(size_t)c * T + q0 + col];
    }

    float O[4][4][4] = {};   // [query i][dim chunk cc][dim j] ; d = cc*64 + tx*4 + j
    float mi[4], li[4];
#pragma unroll
    for (int i = 0; i < 4; i++) { mi[i] = -1e30f; li[i] = 0.f; }

    const float scale = 0.0625f;   // C^-0.5 = 1/16

    for (int s0 = 0; s0 < T; s0 += 64) {
        // ---- Phase A: S[i][j] = sum_c Q[c][q] K[c][s] --------------------
        float S[4][4] = {};
        for (int c0 = 0; c0 < C; c0 += 32) {
            const int krow = ty;            // 0..15
            const int kcol = tx * 4;
            float4 k4a = *(const float4*)&Kb[(size_t)(c0 + krow) * T + s0 + kcol];
            float4 k4b = *(const float4*)&Kb[(size_t)(c0 + krow + 16) * T + s0 + kcol];
            float bs = 0.f;
            if (c0 == 0 && tid < 64) bs = (1.0f - __ldg(&mb[s0 + tid])) * NEG;
            __syncthreads();                // previous consumers done
            *(float4*)&sm->Ks[krow][kcol]      = k4a;
            *(float4*)&sm->Ks[krow + 16][kcol] = k4b;
            if (c0 == 0 && tid < 64) sm->bias_s[tid] = bs;
            __syncthreads();
#pragma unroll 8
            for (int k = 0; k < 32; k++) {
                float4 a4 = *(const float4*)&sm->Qs[c0 + k][ty * 4];
                float4 k4 = *(const float4*)&sm->Ks[k][tx * 4];
                float av[4] = {a4.x, a4.y, a4.z, a4.w};
                float bv[4] = {k4.x, k4.y, k4.z, k4.w};
#pragma unroll
                for (int i = 0; i < 4; i++)
#pragma unroll
                    for (int j = 0; j < 4; j++)
                        S[i][j] = fmaf(av[i], bv[j], S[i][j]);
            }
        }

        // ---- Phase B: online softmax (row stats shared across the 16 tx) --
#pragma unroll
        for (int i = 0; i < 4; i++) {
            float rm = -1e30f;
#pragma unroll
            for (int j = 0; j < 4; j++) {
                float sv = S[i][j] * scale + sm->bias_s[tx * 4 + j];
                S[i][j] = sv;
                rm = fmaxf(rm, sv);
            }
#pragma unroll
            for (int off = 1; off < 16; off <<= 1)
                rm = fmaxf(rm, __shfl_xor_sync(0xffffffffu, rm, off));
            const float mn = fmaxf(mi[i], rm);
            const float al = __expf(mi[i] - mn);
            float rs = 0.f;
#pragma unroll
            for (int j = 0; j < 4; j++) {
                float p = __expf(S[i][j] - mn);
                S[i][j] = p;
                rs += p;
            }
#pragma unroll
            for (int off = 1; off < 16; off <<= 1)
                rs += __shfl_xor_sync(0xffffffffu, rs, off);
            li[i] = li[i] * al + rs;
            mi[i] = mn;
#pragma unroll
            for (int cc = 0; cc < 4; cc++)
#pragma unroll
                for (int j = 0; j < 4; j++)
                    O[i][cc][j] *= al;
        }

        // stage P to smem (all threads already past Phase-A syncs)
#pragma unroll
        for (int i = 0; i < 4; i++)
            *(float4*)&sm->Ps[ty * 4 + i][tx * 4] =
                make_float4(S[i][0], S[i][1], S[i][2], S[i][3]);
        __syncthreads();

        // ---- Phase C: O[q][d] += sum_s P[q][s] V[d][s] --------------------
#pragma unroll
        for (int cc = 0; cc < 4; cc++) {
            if (cc) __syncthreads();
#pragma unroll
            for (int u = 0; u < 4; u++) {
                const int d = (tid >> 4) + u * 16;       // 0..63
                const int kc2 = (tid & 15) * 4;          // key col
                float4 v4 = *(const float4*)&Vb[(size_t)(cc * 64 + d) * T + s0 + kc2];
                sm->Vs[kc2 + 0][d] = v4.x;
                sm->Vs[kc2 + 1][d] = v4.y;
                sm->Vs[kc2 + 2][d] = v4.z;
                sm->Vs[kc2 + 3][d] = v4.w;
            }
            __syncthreads();
#pragma unroll 4
            for (int key = 0; key < 64; key++) {
                float4 v = *(const float4*)&sm->Vs[key][tx * 4];
#pragma unroll
                for (int i = 0; i < 4; i++) {
                    float p = sm->Ps[ty * 4 + i][key];
                    O[i][cc][0] = fmaf(p, v.x, O[i][cc][0]);
                    O[i][cc][1] = fmaf(p, v.y, O[i][cc][1]);
                    O[i][cc][2] = fmaf(p, v.z, O[i][cc][2]);
                    O[i][cc][3] = fmaf(p, v.w, O[i][cc][3]);
                }
            }
        }
    }

    // ---- Epilogue: normalize, transpose through smem, coalesced store ----
#pragma unroll
    for (int i = 0; i < 4; i++) li[i] = 1.0f / li[i];
    float* Ob = g_attn + (size_t)b * C * T;
#pragma unroll
    for (int cc = 0; cc < 4; cc++) {
        __syncthreads();
#pragma unroll
        for (int i = 0; i < 4; i++)
#pragma unroll
            for (int j = 0; j < 4; j++)
                sm->Ps[tx * 4 + j][ty * 4 + i] = O[i][cc][j] * li[i];
        __syncthreads();
#pragma unroll
        for (int u = 0; u < 4; u++) {
            const int d  = (tid >> 4) + u * 16;
            const int qc = (tid & 15) * 4;
            *(float4*)&Ob[(size_t)(cc * 64 + d) * T + q0 + qc] =
                *(const float4*)&sm->Ps[d][qc];
        }
    }
}

// ---------------------------------------------------------------------------
// Launcher: 7 kernel launches, graph-capturable, allocation-free.
// ---------------------------------------------------------------------------
extern "C" void kernel_launch(void* const* d_in, const int* in_sizes, int n_in,
                              void* d_out, int out_size) {
    const float* x     = (const float*)d_in[0];
    const float* xm    = (const float*)d_in[1];
    const float* gamma = (const float*)d_in[2];
    const float* beta  = (const float*)d_in[3];
    const float* Wp    = (const float*)d_in[4];
    const float* bp    = (const float*)d_in[5];
    const float* Wq    = (const float*)d_in[6];
    const float* bq    = (const float*)d_in[7];
    const float* Wk    = (const float*)d_in[8];
    const float* bk    = (const float*)d_in[9];
    const float* Wv    = (const float*)d_in[10];
    const float* bv    = (const float*)d_in[11];
    const float* Wo    = (const float*)d_in[12];
    const float* bo    = (const float*)d_in[13];
    float* out = (float*)d_out;

    float *p_ln, *p_h1, *p_q, *p_k, *p_v, *p_attn;
    cudaGetSymbolAddress((void**)&p_ln,   g_ln);
    cudaGetSymbolAddress((void**)&p_h1,   g_h1);
    cudaGetSymbolAddress((void**)&p_q,    g_qb);
    cudaGetSymbolAddress((void**)&p_k,    g_kb);
    cudaGetSymbolAddress((void**)&p_v,    g_vb);
    cudaGetSymbolAddress((void**)&p_attn, g_attn);

    cudaFuncSetAttribute(attn_kernel, cudaFuncAttributeMaxDynamicSharedMemorySize,
                         (int)sizeof(AttnSmem));

    // 1) masked LayerNorm -> g_ln
    ln_kernel<<<dim3(T / 128, B), 128>>>(x, xm, gamma, beta);

    const dim3 ggrid(T / 64, C / 64, B);
    // 2) h1 = (Wp @ ln + bp) * m
    gemm_kernel<<<ggrid, 256>>>(Wp, bp, p_ln, xm, nullptr, p_h1);
    // 3-5) q,k,v = (W @ h1 + b) * m
    gemm_kernel<<<ggrid, 256>>>(Wq, bq, p_h1, xm, nullptr, p_q);
    gemm_kernel<<<ggrid, 256>>>(Wk, bk, p_h1, xm, nullptr, p_k);
    gemm_kernel<<<ggrid, 256>>>(Wv, bv, p_h1, xm, nullptr, p_v);
    // 6) flash attention -> g_attn
    attn_kernel<<<dim3(T / 64, B), 256, sizeof(AttnSmem)>>>(xm);
    // 7) out = (x + (Wo @ attn + bo) * m) * m
    gemm_kernel<<<ggrid, 256>>>(Wo, bo, p_attn, xm, x, out);
}

// round 14
// speedup vs baseline: 1.0031x; 1.0031x over previous
#include <cuda_runtime.h>
#include <math.h>

// Problem dims (fixed by the reference)
namespace {
constexpr int B = 4, C = 256, T = 4096;
constexpr float EPS = 1e-5f;
constexpr float NEG = -1e8f;
}

// ---------------------------------------------------------------------------
// Scratch buffers (static __device__ arrays — allocation-free per harness rules)
// ---------------------------------------------------------------------------
__device__ float g_ln  [(size_t)B * C * T];
__device__ float g_h1  [(size_t)B * C * T];
__device__ float g_qb  [(size_t)B * C * T];
__device__ float g_kb  [(size_t)B * C * T];
__device__ float g_vb  [(size_t)B * C * T];
__device__ float g_attn[(size_t)B * C * T];

// ---------------------------------------------------------------------------
// Kernel 1: masked LayerNorm over channel dim.
//   h = x * m ; ln[b,c,t] = (h - mu_t) * rsqrt(var_t + eps) * gamma[c] + beta[c]
// Layout [B,C,T]; one thread per (b,t); loops over c are coalesced across t.
// ---------------------------------------------------------------------------
__global__ void ln_kernel(const float* __restrict__ x,
                          const float* __restrict__ mask,
                          const float* __restrict__ gamma,
                          const float* __restrict__ beta) {
    const int b = blockIdx.y;
    const int t = blockIdx.x * blockDim.x + threadIdx.x;
    const float m = mask[(size_t)b * T + t];
    const float* xp = x + (size_t)b * C * T + t;

    float sum = 0.f, sq = 0.f;
#pragma unroll 8
    for (int c = 0; c < C; c++) {
        float v = __ldg(&xp[(size_t)c * T]) * m;
        sum += v;
        sq  += v * v;
    }
    const float mu  = sum * (1.0f / C);
    float var = sq * (1.0f / C) - mu * mu;
    var = fmaxf(var, 0.0f);
    const float rs = rsqrtf(var + EPS);

    float* op = g_ln + (size_t)b * C * T + t;
#pragma unroll 8
    for (int c = 0; c < C; c++) {
        float v = __ldg(&xp[(size_t)c * T]) * m;
        op[(size_t)c * T] = (v - mu) * rs * __ldg(&gamma[c]) + __ldg(&beta[c]);
    }
}

// ---------------------------------------------------------------------------
// Kernel 2: projection GEMM.
//   out[b,o,t] = (sum_c W[o,c] * in[b,c,t] + bias[o]) * mask[b,t]
//   if resid != null: out = (resid + out) * mask   (final Wo + residual path)
// Tiles: 64(M) x 64(N) x 16(K), 256 threads, 4x4 register micro-tile.
// ---------------------------------------------------------------------------
__global__ __launch_bounds__(256) void gemm_kernel(
    const float* __restrict__ W,      // [C, C] row-major (o major, c contiguous)
    const float* __restrict__ bias,   // [C]
    const float* __restrict__ in,     // [B, C, T]
    const float* __restrict__ mask,   // [B, T]
    const float* __restrict__ resid,  // [B, C, T] or nullptr
    float* __restrict__ out)          // [B, C, T]
{
    __shared__ __align__(16) float As[16][68];  // As[k][m]
    __shared__ __align__(16) float Bs[16][68];  // Bs[k][n]

    const int b  = blockIdx.z;
    const int m0 = blockIdx.y * 64;
    const int n0 = blockIdx.x * 64;
    const int tid = threadIdx.x;
    const int tx = tid & 15, ty = tid >> 4;

    const float* inb = in + (size_t)b * C * T;

    float acc[4][4] = {};

    const int arow = tid >> 2;          // 0..63
    const int akc  = (tid & 3) * 4;     // 0,4,8,12
    const int brow = tid >> 4;          // 0..15
    const int bcol = (tid & 15) * 4;    // 0..60

    for (int k0 = 0; k0 < C; k0 += 16) {
        // prefetch to registers
        float4 a4 = *(const float4*)&W[(size_t)(m0 + arow) * C + k0 + akc];
        float4 b4 = *(const float4*)&inb[(size_t)(k0 + brow) * T + n0 + bcol];
        __syncthreads();  // previous tile fully consumed
        As[akc + 0][arow] = a4.x;
        As[akc + 1][arow] = a4.y;
        As[akc + 2][arow] = a4.z;
        As[akc + 3][arow] = a4.w;
        *(float4*)&Bs[brow][bcol] = b4;
        __syncthreads();
#pragma unroll
        for (int k = 0; k < 16; k++) {
            float4 av4 = *(const float4*)&As[k][ty * 4];
            float4 bv4 = *(const float4*)&Bs[k][tx * 4];
            float av[4] = {av4.x, av4.y, av4.z, av4.w};
            float bv[4] = {bv4.x, bv4.y, bv4.z, bv4.w};
#pragma unroll
            for (int i = 0; i < 4; i++)
#pragma unroll
                for (int j = 0; j < 4; j++)
                    acc[i][j] = fmaf(av[i], bv[j], acc[i][j]);
        }
    }

    // epilogue
    const int tglob = n0 + tx * 4;
    float4 mk4 = *(const float4*)&mask[(size_t)b * T + tglob];
    float mk[4] = {mk4.x, mk4.y, mk4.z, mk4.w};

#pragma unroll
    for (int i = 0; i < 4; i++) {
        const int o = m0 + ty * 4 + i;
        const float bo = __ldg(&bias[o]);
        const size_t base = ((size_t)b * C + o) * T + tglob;
        float vals[4];
#pragma unroll
        for (int j = 0; j < 4; j++) vals[j] = (acc[i][j] + bo) * mk[j];
        if (resid != nullptr) {
            float4 x4 = *(const float4*)&resid[base];
            float xr[4] = {x4.x, x4.y, x4.z, x4.w};
#pragma unroll
            for (int j = 0; j < 4; j++) vals[j] = (xr[j] + vals[j]) * mk[j];
        }
        float4 r = make_float4(vals[0], vals[1], vals[2], vals[3]);
        *(float4*)&out[base] = r;
    }
}

// ---------------------------------------------------------------------------
// Kernel 3: flash attention (fp32 SIMT).
//   scores[t,s] = (sum_c q[c,t]*k[c,s]) * C^-0.5 + (1-m[s])*NEG
//   w = softmax_s(scores) ; attn[c,t] = sum_s v[c,s]*w[t,s]
// Block = 64 queries x full key loop (tiles of 64). 256 threads (16x16).
// Q tile (256x64 fp32 = 64KB) resident in smem. Online softmax.
// ---------------------------------------------------------------------------
struct AttnSmem {
    float Qs[256][64];   // Qs[c][q]           65536 B
    float Ks[32][64];    // Ks[c_local][s]      8192 B
    float Ps[64][68];    // Ps[q][s] (padded)  17408 B (reused for output transpose)
    float Vs[64][68];    // Vs[s][d] (padded)  17408 B
    float bias_s[64];    //                      256 B
};                       // total 108800 B

__global__ __launch_bounds__(256, 2) void attn_kernel(const float* __restrict__ mask) {
    extern __shared__ __align__(16) char smraw[];
    AttnSmem* sm = reinterpret_cast<AttnSmem*>(smraw);

    const int b  = blockIdx.y;
    const int q0 = blockIdx.x * 64;
    const int tid = threadIdx.x;
    const int tx = tid & 15, ty = tid >> 4;

    const float* Qb = g_qb + (size_t)b * C * T;
    const float* Kb = g_kb + (size_t)b * C * T;
    const float* Vb = g_vb + (size_t)b * C * T;
    const float* mb = mask + (size_t)b * T;

    // Load Q tile: Qs[c][q] = Q[c][q0+q]
    {
        const int col = (tid & 15) * 4;
        for (int c = tid >> 4; c < C; c += 16)
            *(float4*)&sm->Qs[c][col] = *(const float4*)&Qb[(size_t)c * T + q0 + col];
    }

    float O[4][4][4] = {};   // [query i][dim chunk cc][dim j] ; d = cc*64 + tx*4 + j
    float mi[4], li[4];
#pragma unroll
    for (int i = 0; i < 4; i++) { mi[i] = -1e30f; li[i] = 0.f; }

    const float scale = 0.0625f;   // C^-0.5 = 1/16

    for (int s0 = 0; s0 < T; s0 += 64) {
        // ---- Phase A: S[i][j] = sum_c Q[c][q] K[c][s] --------------------
        float S[4][4] = {};
        for (int c0 = 0; c0 < C; c0 += 32) {
            const int krow = ty;            // 0..15
            const int kcol = tx * 4;
            float4 k4a = *(const float4*)&Kb[(size_t)(c0 + krow) * T + s0 + kcol];
            float4 k4b = *(const float4*)&Kb[(size_t)(c0 + krow + 16) * T + s0 + kcol];
            float bs = 0.f;
            if (c0 == 0 && tid < 64) bs = (1.0f - __ldg(&mb[s0 + tid])) * NEG;
            __syncthreads();                // previous consumers done
            *(float4*)&sm->Ks[krow][kcol]      = k4a;
            *(float4*)&sm->Ks[krow + 16][kcol] = k4b;
            if (c0 == 0 && tid < 64) sm->bias_s[tid] = bs;
            __syncthreads();
#pragma unroll 8
            for (int k = 0; k < 32; k++) {
                float4 a4 = *(const float4*)&sm->Qs[c0 + k][ty * 4];
                float4 k4 = *(const float4*)&sm->Ks[k][tx * 4];
                float av[4] = {a4.x, a4.y, a4.z, a4.w};
                float bv[4] = {k4.x, k4.y, k4.z, k4.w};
#pragma unroll
                for (int i = 0; i < 4; i++)
#pragma unroll
                    for (int j = 0; j < 4; j++)
                        S[i][j] = fmaf(av[i], bv[j], S[i][j]);
            }
        }

        // ---- Phase B: online softmax (row stats shared across the 16 tx) --
#pragma unroll
        for (int i = 0; i < 4; i++) {
            float rm = -1e30f;
#pragma unroll
            for (int j = 0; j < 4; j++) {
                float sv = S[i][j] * scale + sm->bias_s[tx * 4 + j];
                S[i][j] = sv;
                rm = fmaxf(rm, sv);
            }
#pragma unroll
            for (int off = 1; off < 16; off <<= 1)
                rm = fmaxf(rm, __shfl_xor_sync(0xffffffffu, rm, off));
            const float mn = fmaxf(mi[i], rm);
            const float al = __expf(mi[i] - mn);
            float rs = 0.f;
#pragma unroll
            for (int j = 0; j < 4; j++) {
                float p = __expf(S[i][j] - mn);
                S[i][j] = p;
                rs += p;
            }
#pragma unroll
            for (int off = 1; off < 16; off <<= 1)
                rs += __shfl_xor_sync(0xffffffffu, rs, off);
            li[i] = li[i] * al + rs;
            mi[i] = mn;
#pragma unroll
            for (int cc = 0; cc < 4; cc++)
#pragma unroll
                for (int j = 0; j < 4; j++)
                    O[i][cc][j] *= al;
        }

        // stage P to smem (all threads already past Phase-A syncs)
#pragma unroll
        for (int i = 0; i < 4; i++)
            *(float4*)&sm->Ps[ty * 4 + i][tx * 4] =
                make_float4(S[i][0], S[i][1], S[i][2], S[i][3]);
        __syncthreads();

        // ---- Phase C: O[q][d] += sum_s P[q][s] V[d][s] --------------------
#pragma unroll
        for (int cc = 0; cc < 4; cc++) {
            if (cc) __syncthreads();
#pragma unroll
            for (int u = 0; u < 4; u++) {
                const int d = (tid >> 4) + u * 16;       // 0..63
                const int kc2 = (tid & 15) * 4;          // key col
                float4 v4 = *(const float4*)&Vb[(size_t)(cc * 64 + d) * T + s0 + kc2];
                sm->Vs[kc2 + 0][d] = v4.x;
                sm->Vs[kc2 + 1][d] = v4.y;
                sm->Vs[kc2 + 2][d] = v4.z;
                sm->Vs[kc2 + 3][d] = v4.w;
            }
            __syncthreads();
#pragma unroll 4
            for (int key = 0; key < 64; key++) {
                float4 v = *(const float4*)&sm->Vs[key][tx * 4];
#pragma unroll
                for (int i = 0; i < 4; i++) {
                    float p = sm->Ps[ty * 4 + i][key];
                    O[i][cc][0] = fmaf(p, v.x, O[i][cc][0]);
                    O[i][cc][1] = fmaf(p, v.y, O[i][cc][1]);
                    O[i][cc][2] = fmaf(p, v.z, O[i][cc][2]);
                    O[i][cc][3] = fmaf(p, v.w, O[i][cc][3]);
                }
            }
        }
    }

    // ---- Epilogue: normalize, transpose through smem, coalesced store ----
#pragma unroll
    for (int i = 0; i < 4; i++) li[i] = 1.0f / li[i];
    float* Ob = g_attn + (size_t)b * C * T;
#pragma unroll
    for (int cc = 0; cc < 4; cc++) {
        __syncthreads();
#pragma unroll
        for (int i = 0; i < 4; i++)
#pragma unroll
            for (int j = 0; j < 4; j++)
                sm->Ps[tx * 4 + j][ty * 4 + i] = O[i][cc][j] * li[i];
        __syncthreads();
#pragma unroll
        for (int u = 0; u < 4; u++) {
            const int d  = (tid >> 4) + u * 16;
            const int qc = (tid & 15) * 4;
            *(float4*)&Ob[(size_t)(cc * 64 + d) * T + q0 + qc] =
                *(const float4*)&sm->Ps[d][qc];
        }
    }
}

// ---------------------------------------------------------------------------
// Launcher: 7 kernel launches, graph-capturable, allocation-free.
// ---------------------------------------------------------------------------
extern "C" void kernel_launch(void* const* d_in, const int* in_sizes, int n_in,
                              void* d_out, int out_size) {
    const float* x     = (const float*)d_in[0];
    const float* xm    = (const float*)d_in[1];
    const float* gamma = (const float*)d_in[2];
    const float* beta  = (const float*)d_in[3];
    const float* Wp    = (const float*)d_in[4];
    const float* bp    = (const float*)d_in[5];
    const float* Wq    = (const float*)d_in[6];
    const float* bq    = (const float*)d_in[7];
    const float* Wk    = (const float*)d_in[8];
    const float* bk    = (const float*)d_in[9];
    const float* Wv    = (const float*)d_in[10];
    const float* bv    = (const float*)d_in[11];
    const float* Wo    = (const float*)d_in[12];
    const float* bo    = (const float*)d_in[13];
    float* out = (float*)d_out;

    float *p_ln, *p_h1, *p_q, *p_k, *p_v, *p_attn;
    cudaGetSymbolAddress((void**)&p_ln,   g_ln);
    cudaGetSymbolAddress((void**)&p_h1,   g_h1);
    cudaGetSymbolAddress((void**)&p_q,    g_qb);
    cudaGetSymbolAddress((void**)&p_k,    g_kb);
    cudaGetSymbolAddress((void**)&p_v,    g_vb);
    cudaGetSymbolAddress((void**)&p_attn, g_attn);

    cudaFuncSetAttribute(attn_kernel, cudaFuncAttributeMaxDynamicSharedMemorySize,
                         (int)sizeof(AttnSmem));

    // 1) masked LayerNorm -> g_ln
    ln_kernel<<<dim3(T / 128, B), 128>>>(x, xm, gamma, beta);

    const dim3 ggrid(T / 64, C / 64, B);
    // 2) h1 = (Wp @ ln + bp) * m
    gemm_kernel<<<ggrid, 256>>>(Wp, bp, p_ln, xm, nullptr, p_h1);
    // 3-5) q,k,v = (W @ h1 + b) * m
    gemm_kernel<<<ggrid, 256>>>(Wq, bq, p_h1, xm, nullptr, p_q);
    gemm_kernel<<<ggrid, 256>>>(Wk, bk, p_h1, xm, nullptr, p_k);
    gemm_kernel<<<ggrid, 256>>>(Wv, bv, p_h1, xm, nullptr, p_v);
    // 6) flash attention -> g_attn
    attn_kernel<<<dim3(T / 64, B), 256, sizeof(AttnSmem)>>>(xm);
    // 7) out = (x + (Wo @ attn + bo) * m) * m
    gemm_kernel<<<ggrid, 256>>>(Wo, bo, p_attn, xm, x, out);
}

// round 15
// speedup vs baseline: 1.0040x; 1.0009x over previous
#include <cuda_runtime.h>
#include <math.h>

// Problem dims (fixed by the reference)
namespace {
constexpr int B = 4, C = 256, T = 4096;
constexpr float EPS = 1e-5f;
constexpr float NEG = -1e8f;
}

// ---------------------------------------------------------------------------
// Scratch buffers (static __device__ arrays — allocation-free per harness rules)
// ---------------------------------------------------------------------------
__device__ float g_ln  [(size_t)B * C * T];
__device__ float g_h1  [(size_t)B * C * T];
__device__ float g_qb  [(size_t)B * C * T];
__device__ float g_kb  [(size_t)B * C * T];
__device__ float g_vb  [(size_t)B * C * T];
__device__ float g_attn[(size_t)B * C * T];

// ---------------------------------------------------------------------------
// Kernel 1: masked LayerNorm over channel dim.
//   h = x * m ; ln[b,c,t] = (h - mu_t) * rsqrt(var_t + eps) * gamma[c] + beta[c]
// Layout [B,C,T]; one thread per (b,t); loops over c are coalesced across t.
// ---------------------------------------------------------------------------
__global__ void ln_kernel(const float* __restrict__ x,
                          const float* __restrict__ mask,
                          const float* __restrict__ gamma,
                          const float* __restrict__ beta) {
    const int b = blockIdx.y;
    const int t = blockIdx.x * blockDim.x + threadIdx.x;
    const float m = mask[(size_t)b * T + t];
    const float* xp = x + (size_t)b * C * T + t;

    float sum = 0.f, sq = 0.f;
#pragma unroll 8
    for (int c = 0; c < C; c++) {
        float v = __ldg(&xp[(size_t)c * T]) * m;
        sum += v;
        sq  += v * v;
    }
    const float mu  = sum * (1.0f / C);
    float var = sq * (1.0f / C) - mu * mu;
    var = fmaxf(var, 0.0f);
    const float rs = rsqrtf(var + EPS);

    float* op = g_ln + (size_t)b * C * T + t;
#pragma unroll 8
    for (int c = 0; c < C; c++) {
        float v = __ldg(&xp[(size_t)c * T]) * m;
        op[(size_t)c * T] = (v - mu) * rs * __ldg(&gamma[c]) + __ldg(&beta[c]);
    }
}

// ---------------------------------------------------------------------------
// Kernel 2: projection GEMM.
//   out[b,o,t] = (sum_c W[o,c] * in[b,c,t] + bias[o]) * mask[b,t]
//   if resid != null: out = (resid + out) * mask   (final Wo + residual path)
// Tiles: 64(M) x 64(N) x 16(K), 256 threads, 4x4 register micro-tile.
// ---------------------------------------------------------------------------
__global__ __launch_bounds__(256) void gemm_kernel(
    const float* __restrict__ W,      // [C, C] row-major (o major, c contiguous)
    const float* __restrict__ bias,   // [C]
    const float* __restrict__ in,     // [B, C, T]
    const float* __restrict__ mask,   // [B, T]
    const float* __restrict__ resid,  // [B, C, T] or nullptr
    float* __restrict__ out)          // [B, C, T]
{
    __shared__ __align__(16) float As[16][68];  // As[k][m]
    __shared__ __align__(16) float Bs[16][68];  // Bs[k][n]

    const int b  = blockIdx.z;
    const int m0 = blockIdx.y * 64;
    const int n0 = blockIdx.x * 64;
    const int tid = threadIdx.x;
    const int tx = tid & 15, ty = tid >> 4;

    const float* inb = in + (size_t)b * C * T;

    float acc[4][4] = {};

    const int arow = tid >> 2;          // 0..63
    const int akc  = (tid & 3) * 4;     // 0,4,8,12
    const int brow = tid >> 4;          // 0..15
    const int bcol = (tid & 15) * 4;    // 0..60

    for (int k0 = 0; k0 < C; k0 += 16) {
        // prefetch to registers
        float4 a4 = *(const float4*)&W[(size_t)(m0 + arow) * C + k0 + akc];
        float4 b4 = *(const float4*)&inb[(size_t)(k0 + brow) * T + n0 + bcol];
        __syncthreads();  // previous tile fully consumed
        As[akc + 0][arow] = a4.x;
        As[akc + 1][arow] = a4.y;
        As[akc + 2][arow] = a4.z;
        As[akc + 3][arow] = a4.w;
        *(float4*)&Bs[brow][bcol] = b4;
        __syncthreads();
#pragma unroll
        for (int k = 0; k < 16; k++) {
            float4 av4 = *(const float4*)&As[k][ty * 4];
            float4 bv4 = *(const float4*)&Bs[k][tx * 4];
            float av[4] = {av4.x, av4.y, av4.z, av4.w};
            float bv[4] = {bv4.x, bv4.y, bv4.z, bv4.w};
#pragma unroll
            for (int i = 0; i < 4; i++)
#pragma unroll
                for (int j = 0; j < 4; j++)
                    acc[i][j] = fmaf(av[i], bv[j], acc[i][j]);
        }
    }

    // epilogue
    const int tglob = n0 + tx * 4;
    float4 mk4 = *(const float4*)&mask[(size_t)b * T + tglob];
    float mk[4] = {mk4.x, mk4.y, mk4.z, mk4.w};

#pragma unroll
    for (int i = 0; i < 4; i++) {
        const int o = m0 + ty * 4 + i;
        const float bo = __ldg(&bias[o]);
        const size_t base = ((size_t)b * C + o) * T + tglob;
        float vals[4];
#pragma unroll
        for (int j = 0; j < 4; j++) vals[j] = (acc[i][j] + bo) * mk[j];
        if (resid != nullptr) {
            float4 x4 = *(const float4*)&resid[base];
            float xr[4] = {x4.x, x4.y, x4.z, x4.w};
#pragma unroll
            for (int j = 0; j < 4; j++) vals[j] = (xr[j] + vals[j]) * mk[j];
        }
        float4 r = make_float4(vals[0], vals[1], vals[2], vals[3]);
        *(float4*)&out[base] = r;
    }
}

// ---------------------------------------------------------------------------
// Kernel 3: flash attention (fp32 SIMT).
//   scores[t,s] = (sum_c q[c,t]*k[c,s]) * C^-0.5 + (1-m[s])*NEG
//   w = softmax_s(scores) ; attn[c,t] = sum_s v[c,s]*w[t,s]
// Block = 64 queries x full key loop (tiles of 64). 256 threads (16x16).
// Q tile (256x64 fp32 = 64KB) resident in smem. Online softmax.
// ---------------------------------------------------------------------------
struct AttnSmem {
    float Qs[256][64];   // Qs[c][q]           65536 B
    float Ks[32][64];    // Ks[c_local][s]      8192 B
    float Ps[64][68];    // Ps[q][s] (padded)  17408 B (reused for output transpose)
    float Vs[64][68];    // Vs[s][d] (padded)  17408 B
    float bias_s[64];    //                      256 B
};                       // total 108800 B

__global__ __launch_bounds__(256, 2) void attn_kernel(const float* __restrict__ mask) {
    extern __shared__ __align__(16) char smraw[];
    AttnSmem* sm = reinterpret_cast<AttnSmem*>(smraw);

    const int b  = blockIdx.y;
    const int q0 = blockIdx.x * 64;
    const int tid = threadIdx.x;
    const int tx = tid & 15, ty = tid >> 4;

    const float* Qb = g_qb + (size_t)b * C * T;
    const float* Kb = g_kb + (size_t)b * C * T;
    const float* Vb = g_vb + (size_t)b * C * T;
    const float* mb = mask + (size_t)b * T;

    // Load Q tile: Qs[c][q] = Q[c][q0+q]
    {
        const int col = (tid & 15) * 4;
        for (int c = tid >> 4; c < C; c += 16)
            *(float4*)&sm->Qs[c][col] = *(const float4*)&Qb[(size_t)c * T + q0 + col];
    }

    float O[4][4][4] = {};   // [query i][dim chunk cc][dim j] ; d = cc*64 + tx*4 + j
    float mi[4], li[4];
#pragma unroll
    for (int i = 0; i < 4; i++) { mi[i] = -1e30f; li[i] = 0.f; }

    const float scale = 0.0625f;   // C^-0.5 = 1/16

    for (int s0 = 0; s0 < T; s0 += 64) {
        // ---- Phase A: S[i][j] = sum_c Q[c][q] K[c][s] --------------------
        float S[4][4] = {};
        for (int c0 = 0; c0 < C; c0 += 32) {
            const int krow = ty;            // 0..15
            const int kcol = tx * 4;
            float4 k4a = *(const float4*)&Kb[(size_t)(c0 + krow) * T + s0 + kcol];
            float4 k4b = *(const float4*)&Kb[(size_t)(c0 + krow + 16) * T + s0 + kcol];
            float bs = 0.f;
            if (c0 == 0 && tid < 64) bs = (1.0f - __ldg(&mb[s0 + tid])) * NEG;
            __syncthreads();                // previous consumers done
            *(float4*)&sm->Ks[krow][kcol]      = k4a;
            *(float4*)&sm->Ks[krow + 16][kcol] = k4b;
            if (c0 == 0 && tid < 64) sm->bias_s[tid] = bs;
            __syncthreads();
#pragma unroll 8
            for (int k = 0; k < 32; k++) {
                float4 a4 = *(const float4*)&sm->Qs[c0 + k][ty * 4];
                float4 k4 = *(const float4*)&sm->Ks[k][tx * 4];
                float av[4] = {a4.x, a4.y, a4.z, a4.w};
                float bv[4] = {k4.x, k4.y, k4.z, k4.w};
#pragma unroll
                for (int i = 0; i < 4; i++)
#pragma unroll
                    for (int j = 0; j < 4; j++)
                        S[i][j] = fmaf(av[i], bv[j], S[i][j]);
            }
        }

        // ---- Phase B: online softmax (row stats shared across the 16 tx) --
#pragma unroll
        for (int i = 0; i < 4; i++) {
            float rm = -1e30f;
#pragma unroll
            for (int j = 0; j < 4; j++) {
                float sv = S[i][j] * scale + sm->bias_s[tx * 4 + j];
                S[i][j] = sv;
                rm = fmaxf(rm, sv);
            }
#pragma unroll
            for (int off = 1; off < 16; off <<= 1)
                rm = fmaxf(rm, __shfl_xor_sync(0xffffffffu, rm, off));
            const float mn = fmaxf(mi[i], rm);
            const float al = __expf(mi[i] - mn);
            float rs = 0.f;
#pragma unroll
            for (int j = 0; j < 4; j++) {
                float p = __expf(S[i][j] - mn);
                S[i][j] = p;
                rs += p;
            }
#pragma unroll
            for (int off = 1; off < 16; off <<= 1)
                rs += __shfl_xor_sync(0xffffffffu, rs, off);
            li[i] = li[i] * al + rs;
            mi[i] = mn;
#pragma unroll
            for (int cc = 0; cc < 4; cc++)
#pragma unroll
                for (int j = 0; j < 4; j++)
                    O[i][cc][j] *= al;
        }

        // stage P to smem (all threads already past Phase-A syncs)
#pragma unroll
        for (int i = 0; i < 4; i++)
            *(float4*)&sm->Ps[ty * 4 + i][tx * 4] =
                make_float4(S[i][0], S[i][1], S[i][2], S[i][3]);
        __syncthreads();

        // ---- Phase C: O[q][d] += sum_s P[q][s] V[d][s] --------------------
#pragma unroll
        for (int cc = 0; cc < 4; cc++) {
            if (cc) __syncthreads();
#pragma unroll
            for (int u = 0; u < 4; u++) {
                const int d = (tid >> 4) + u * 16;       // 0..63
                const int kc2 = (tid & 15) * 4;          // key col
                float4 v4 = *(const float4*)&Vb[(size_t)(cc * 64 + d) * T + s0 + kc2];
                sm->Vs[kc2 + 0][d] = v4.x;
                sm->Vs[kc2 + 1][d] = v4.y;
                sm->Vs[kc2 + 2][d] = v4.z;
                sm->Vs[kc2 + 3][d] = v4.w;
            }
            __syncthreads();
#pragma unroll 4
            for (int key = 0; key < 64; key++) {
                float4 v = *(const float4*)&sm->Vs[key][tx * 4];
#pragma unroll
                for (int i = 0; i < 4; i++) {
                    float p = sm->Ps[ty * 4 + i][key];
                    O[i][cc][0] = fmaf(p, v.x, O[i][cc][0]);
                    O[i][cc][1] = fmaf(p, v.y, O[i][cc][1]);
                    O[i][cc][2] = fmaf(p, v.z, O[i][cc][2]);
                    O[i][cc][3] = fmaf(p, v.w, O[i][cc][3]);
                }
            }
        }
    }

    // ---- Epilogue: normalize, transpose through smem, coalesced store ----
#pragma unroll
    for (int i = 0; i < 4; i++) li[i] = 1.0f / li[i];
    float* Ob = g_attn + (size_t)b * C * T;
#pragma unroll
    for (int cc = 0; cc < 4; cc++) {
        __syncthreads();
#pragma unroll
        for (int i = 0; i < 4; i++)
#pragma unroll
            for (int j = 0; j < 4; j++)
                sm->Ps[tx * 4 + j][ty * 4 + i] = O[i][cc][j] * li[i];
        __syncthreads();
#pragma unroll
        for (int u = 0; u < 4; u++) {
            const int d  = (tid >> 4) + u * 16;
            const int qc = (tid & 15) * 4;
            *(float4*)&Ob[(size_t)(cc * 64 + d) * T + q0 + qc] =
                *(const float4*)&sm->Ps[d][qc];
        }
    }
}

// ---------------------------------------------------------------------------
// Launcher: 7 kernel launches, graph-capturable, allocation-free.
// ---------------------------------------------------------------------------
extern "C" void kernel_launch(void* const* d_in, const int* in_sizes, int n_in,
                              void* d_out, int out_size) {
    const float* x     = (const float*)d_in[0];
    const float* xm    = (const float*)d_in[1];
    const float* gamma = (const float*)d_in[2];
    const float* beta  = (const float*)d_in[3];
    const float* Wp    = (const float*)d_in[4];
    const float* bp    = (const float*)d_in[5];
    const float* Wq    = (const float*)d_in[6];
    const float* bq    = (const float*)d_in[7];
    const float* Wk    = (const float*)d_in[8];
    const float* bk    = (const float*)d_in[9];
    const float* Wv    = (const float*)d_in[10];
    const float* bv    = (const float*)d_in[11];
    const float* Wo    = (const float*)d_in[12];
    const float* bo    = (const float*)d_in[13];
    float* out = (float*)d_out;

    float *p_ln, *p_h1, *p_q, *p_k, *p_v, *p_attn;
    cudaGetSymbolAddress((void**)&p_ln,   g_ln);
    cudaGetSymbolAddress((void**)&p_h1,   g_h1);
    cudaGetSymbolAddress((void**)&p_q,    g_qb);
    cudaGetSymbolAddress((void**)&p_k,    g_kb);
    cudaGetSymbolAddress((void**)&p_v,    g_vb);
    cudaGetSymbolAddress((void**)&p_attn, g_attn);

    cudaFuncSetAttribute(attn_kernel, cudaFuncAttributeMaxDynamicSharedMemorySize,
                         (int)sizeof(AttnSmem));

    // 1) masked LayerNorm -> g_ln
    ln_kernel<<<dim3(T / 128, B), 128>>>(x, xm, gamma, beta);

    const dim3 ggrid(T / 64, C / 64, B);
    // 2) h1 = (Wp @ ln + bp) * m
    gemm_kernel<<<ggrid, 256>>>(Wp, bp, p_ln, xm, nullptr, p_h1);
    // 3-5) q,k,v = (W @ h1 + b) * m
    gemm_kernel<<<ggrid, 256>>>(Wq, bq, p_h1, xm, nullptr, p_q);
    gemm_kernel<<<ggrid, 256>>>(Wk, bk, p_h1, xm, nullptr, p_k);
    gemm_kernel<<<ggrid, 256>>>(Wv, bv, p_h1, xm, nullptr, p_v);
    // 6) flash attention -> g_attn
    attn_kernel<<<dim3(T / 64, B), 256, sizeof(AttnSmem)>>>(xm);
    // 7) out = (x + (Wo @ attn + bo) * m) * m
    gemm_kernel<<<ggrid, 256>>>(Wo, bo, p_attn, xm, x, out);
}

// round 16
// speedup vs baseline: 1.0067x; 1.0026x over previous
#include <cuda_runtime.h>
#include <math.h>

// Problem dims (fixed by the reference)
namespace {
constexpr int B = 4, C = 256, T = 4096;
constexpr float EPS = 1e-5f;
constexpr float NEG = -1e8f;
}

// ---------------------------------------------------------------------------
// Scratch buffers (static __device__ arrays — allocation-free per harness rules)
// ---------------------------------------------------------------------------
__device__ float g_ln  [(size_t)B * C * T];
__device__ float g_h1  [(size_t)B * C * T];
__device__ float g_qb  [(size_t)B * C * T];
__device__ float g_kb  [(size_t)B * C * T];
__device__ float g_vb  [(size_t)B * C * T];
__device__ float g_attn[(size_t)B * C * T];

// ---------------------------------------------------------------------------
// Kernel 1: masked LayerNorm over channel dim.
//   h = x * m ; ln[b,c,t] = (h - mu_t) * rsqrt(var_t + eps) * gamma[c] + beta[c]
// Layout [B,C,T]; one thread per (b,t); loops over c are coalesced across t.
// ---------------------------------------------------------------------------
__global__ void ln_kernel(const float* __restrict__ x,
                          const float* __restrict__ mask,
                          const float* __restrict__ gamma,
                          const float* __restrict__ beta) {
    const int b = blockIdx.y;
    const int t = blockIdx.x * blockDim.x + threadIdx.x;
    const float m = mask[(size_t)b * T + t];
    const float* xp = x + (size_t)b * C * T + t;

    float sum = 0.f, sq = 0.f;
#pragma unroll 8
    for (int c = 0; c < C; c++) {
        float v = __ldg(&xp[(size_t)c * T]) * m;
        sum += v;
        sq  += v * v;
    }
    const float mu  = sum * (1.0f / C);
    float var = sq * (1.0f / C) - mu * mu;
    var = fmaxf(var, 0.0f);
    const float rs = rsqrtf(var + EPS);

    float* op = g_ln + (size_t)b * C * T + t;
#pragma unroll 8
    for (int c = 0; c < C; c++) {
        float v = __ldg(&xp[(size_t)c * T]) * m;
        op[(size_t)c * T] = (v - mu) * rs * __ldg(&gamma[c]) + __ldg(&beta[c]);
    }
}

// ---------------------------------------------------------------------------
// Kernel 2: projection GEMM.
//   out[b,o,t] = (sum_c W[o,c] * in[b,c,t] + bias[o]) * mask[b,t]
//   if resid != null: out = (resid + out) * mask   (final Wo + residual path)
// Tiles: 64(M) x 64(N) x 16(K), 256 threads, 4x4 register micro-tile.
// ---------------------------------------------------------------------------
__global__ __launch_bounds__(256) void gemm_kernel(
    const float* __restrict__ W,      // [C, C] row-major (o major, c contiguous)
    const float* __restrict__ bias,   // [C]
    const float* __restrict__ in,     // [B, C, T]
    const float* __restrict__ mask,   // [B, T]
    const float* __restrict__ resid,  // [B, C, T] or nullptr
    float* __restrict__ out)          // [B, C, T]
{
    __shared__ __align__(16) float As[16][68];  // As[k][m]
    __shared__ __align__(16) float Bs[16][68];  // Bs[k][n]

    const int b  = blockIdx.z;
    const int m0 = blockIdx.y * 64;
    const int n0 = blockIdx.x * 64;
    const int tid = threadIdx.x;
    const int tx = tid & 15, ty = tid >> 4;

    const float* inb = in + (size_t)b * C * T;

    float acc[4][4] = {};

    const int arow = tid >> 2;          // 0..63
    const int akc  = (tid & 3) * 4;     // 0,4,8,12
    const int brow = tid >> 4;          // 0..15
    const int bcol = (tid & 15) * 4;    // 0..60

    for (int k0 = 0; k0 < C; k0 += 16) {
        // prefetch to registers
        float4 a4 = *(const float4*)&W[(size_t)(m0 + arow) * C + k0 + akc];
        float4 b4 = *(const float4*)&inb[(size_t)(k0 + brow) * T + n0 + bcol];
        __syncthreads();  // previous tile fully consumed
        As[akc + 0][arow] = a4.x;
        As[akc + 1][arow] = a4.y;
        As[akc + 2][arow] = a4.z;
        As[akc + 3][arow] = a4.w;
        *(float4*)&Bs[brow][bcol] = b4;
        __syncthreads();
#pragma unroll
        for (int k = 0; k < 16; k++) {
            float4 av4 = *(const float4*)&As[k][ty * 4];
            float4 bv4 = *(const float4*)&Bs[k][tx * 4];
            float av[4] = {av4.x, av4.y, av4.z, av4.w};
            float bv[4] = {bv4.x, bv4.y, bv4.z, bv4.w};
#pragma unroll
            for (int i = 0; i < 4; i++)
#pragma unroll
                for (int j = 0; j < 4; j++)
                    acc[i][j] = fmaf(av[i], bv[j], acc[i][j]);
        }
    }

    // epilogue
    const int tglob = n0 + tx * 4;
    float4 mk4 = *(const float4*)&mask[(size_t)b * T + tglob];
    float mk[4] = {mk4.x, mk4.y, mk4.z, mk4.w};

#pragma unroll
    for (int i = 0; i < 4; i++) {
        const int o = m0 + ty * 4 + i;
        const float bo = __ldg(&bias[o]);
        const size_t base = ((size_t)b * C + o) * T + tglob;
        float vals[4];
#pragma unroll
        for (int j = 0; j < 4; j++) vals[j] = (acc[i][j] + bo) * mk[j];
        if (resid != nullptr) {
            float4 x4 = *(const float4*)&resid[base];
            float xr[4] = {x4.x, x4.y, x4.z, x4.w};
#pragma unroll
            for (int j = 0; j < 4; j++) vals[j] = (xr[j] + vals[j]) * mk[j];
        }
        float4 r = make_float4(vals[0], vals[1], vals[2], vals[3]);
        *(float4*)&out[base] = r;
    }
}

// ---------------------------------------------------------------------------
// Kernel 3: flash attention (fp32 SIMT).
//   scores[t,s] = (sum_c q[c,t]*k[c,s]) * C^-0.5 + (1-m[s])*NEG
//   w = softmax_s(scores) ; attn[c,t] = sum_s v[c,s]*w[t,s]
// Block = 64 queries x full key loop (tiles of 64). 256 threads (16x16).
// Q tile (256x64 fp32 = 64KB) resident in smem. Online softmax.
// ---------------------------------------------------------------------------
struct AttnSmem {
    float Qs[256][64];   // Qs[c][q]           65536 B
    float Ks[32][64];    // Ks[c_local][s]      8192 B
    float Ps[64][68];    // Ps[q][s] (padded)  17408 B (reused for output transpose)
    float Vs[64][68];    // Vs[s][d] (padded)  17408 B
    float bias_s[64];    //                      256 B
};                       // total 108800 B

__global__ __launch_bounds__(256, 2) void attn_kernel(const float* __restrict__ mask) {
    extern __shared__ __align__(16) char smraw[];
    AttnSmem* sm = reinterpret_cast<AttnSmem*>(smraw);

    const int b  = blockIdx.y;
    const int q0 = blockIdx.x * 64;
    const int tid = threadIdx.x;
    const int tx = tid & 15, ty = tid >> 4;

    const float* Qb = g_qb + (size_t)b * C * T;
    const float* Kb = g_kb + (size_t)b * C * T;
    const float* Vb = g_vb + (size_t)b * C * T;
    const float* mb = mask + (size_t)b * T;

    // Load Q tile: Qs[c][q] = Q[c][q0+q]
    {
        const int col = (tid & 15) * 4;
        for (int c = tid >> 4; c < C; c += 16)
            *(float4*)&sm->Qs[c][col] = *(const float4*)&Qb[(size_t)c * T + q0 + col];
    }

    float O[4][4][4] = {};   // [query i][dim chunk cc][dim j] ; d = cc*64 + tx*4 + j
    float mi[4], li[4];
#pragma unroll
    for (int i = 0; i < 4; i++) { mi[i] = -1e30f; li[i] = 0.f; }

    const float scale = 0.0625f;   // C^-0.5 = 1/16

    for (int s0 = 0; s0 < T; s0 += 64) {
        // ---- Phase A: S[i][j] = sum_c Q[c][q] K[c][s] --------------------
        float S[4][4] = {};
        for (int c0 = 0; c0 < C; c0 += 32) {
            const int krow = ty;            // 0..15
            const int kcol = tx * 4;
            float4 k4a = *(const float4*)&Kb[(size_t)(c0 + krow) * T + s0 + kcol];
            float4 k4b = *(const float4*)&Kb[(size_t)(c0 + krow + 16) * T + s0 + kcol];
            float bs = 0.f;
            if (c0 == 0 && tid < 64) bs = (1.0f - __ldg(&mb[s0 + tid])) * NEG;
            __syncthreads();                // previous consumers done
            *(float4*)&sm->Ks[krow][kcol]      = k4a;
            *(float4*)&sm->Ks[krow + 16][kcol] = k4b;
            if (c0 == 0 && tid < 64) sm->bias_s[tid] = bs;
            __syncthreads();
#pragma unroll 8
            for (int k = 0; k < 32; k++) {
                float4 a4 = *(const float4*)&sm->Qs[c0 + k][ty * 4];
                float4 k4 = *(const float4*)&sm->Ks[k][tx * 4];
                float av[4] = {a4.x, a4.y, a4.z, a4.w};
                float bv[4] = {k4.x, k4.y, k4.z, k4.w};
#pragma unroll
                for (int i = 0; i < 4; i++)
#pragma unroll
                    for (int j = 0; j < 4; j++)
                        S[i][j] = fmaf(av[i], bv[j], S[i][j]);
            }
        }

        // ---- Phase B: online softmax (row stats shared across the 16 tx) --
#pragma unroll
        for (int i = 0; i < 4; i++) {
            float rm = -1e30f;
#pragma unroll
            for (int j = 0; j < 4; j++) {
                float sv = S[i][j] * scale + sm->bias_s[tx * 4 + j];
                S[i][j] = sv;
                rm = fmaxf(rm, sv);
            }
#pragma unroll
            for (int off = 1; off < 16; off <<= 1)
                rm = fmaxf(rm, __shfl_xor_sync(0xffffffffu, rm, off));
            const float mn = fmaxf(mi[i], rm);
            const float al = __expf(mi[i] - mn);
            float rs = 0.f;
#pragma unroll
            for (int j = 0; j < 4; j++) {
                float p = __expf(S[i][j] - mn);
                S[i][j] = p;
                rs += p;
            }
#pragma unroll
            for (int off = 1; off < 16; off <<= 1)
                rs += __shfl_xor_sync(0xffffffffu, rs, off);
            li[i] = li[i] * al + rs;
            mi[i] = mn;
#pragma unroll
            for (int cc = 0; cc < 4; cc++)
#pragma unroll
                for (int j = 0; j < 4; j++)
                    O[i][cc][j] *= al;
        }

        // stage P to smem (all threads already past Phase-A syncs)
#pragma unroll
        for (int i = 0; i < 4; i++)
            *(float4*)&sm->Ps[ty * 4 + i][tx * 4] =
                make_float4(S[i][0], S[i][1], S[i][2], S[i][3]);
        __syncthreads();

        // ---- Phase C: O[q][d] += sum_s P[q][s] V[d][s] --------------------
#pragma unroll
        for (int cc = 0; cc < 4; cc++) {
            if (cc) __syncthreads();
#pragma unroll
            for (int u = 0; u < 4; u++) {
                const int d = (tid >> 4) + u * 16;       // 0..63
                const int kc2 = (tid & 15) * 4;          // key col
                float4 v4 = *(const float4*)&Vb[(size_t)(cc * 64 + d) * T + s0 + kc2];
                sm->Vs[kc2 + 0][d] = v4.x;
                sm->Vs[kc2 + 1][d] = v4.y;
                sm->Vs[kc2 + 2][d] = v4.z;
                sm->Vs[kc2 + 3][d] = v4.w;
            }
            __syncthreads();
#pragma unroll 4
            for (int key = 0; key < 64; key++) {
                float4 v = *(const float4*)&sm->Vs[key][tx * 4];
#pragma unroll
                for (int i = 0; i < 4; i++) {
                    float p = sm->Ps[ty * 4 + i][key];
                    O[i][cc][0] = fmaf(p, v.x, O[i][cc][0]);
                    O[i][cc][1] = fmaf(p, v.y, O[i][cc][1]);
                    O[i][cc][2] = fmaf(p, v.z, O[i][cc][2]);
                    O[i][cc][3] = fmaf(p, v.w, O[i][cc][3]);
                }
            }
        }
    }

    // ---- Epilogue: normalize, transpose through smem, coalesced store ----
#pragma unroll
    for (int i = 0; i < 4; i++) li[i] = 1.0f / li[i];
    float* Ob = g_attn + (size_t)b * C * T;
#pragma unroll
    for (int cc = 0; cc < 4; cc++) {
        __syncthreads();
#pragma unroll
        for (int i = 0; i < 4; i++)
#pragma unroll
            for (int j = 0; j < 4; j++)
                sm->Ps[tx * 4 + j][ty * 4 + i] = O[i][cc][j] * li[i];
        __syncthreads();
#pragma unroll
        for (int u = 0; u < 4; u++) {
            const int d  = (tid >> 4) + u * 16;
            const int qc = (tid & 15) * 4;
            *(float4*)&Ob[(size_t)(cc * 64 + d) * T + q0 + qc] =
                *(const float4*)&sm->Ps[d][qc];
        }
    }
}

// ---------------------------------------------------------------------------
// Launcher: 7 kernel launches, graph-capturable, allocation-free.
// ---------------------------------------------------------------------------
extern "C" void kernel_launch(void* const* d_in, const int* in_sizes, int n_in,
                              void* d_out, int out_size) {
    const float* x     = (const float*)d_in[0];
    const float* xm    = (const float*)d_in[1];
    const float* gamma = (const float*)d_in[2];
    const float* beta  = (const float*)d_in[3];
    const float* Wp    = (const float*)d_in[4];
    const float* bp    = (const float*)d_in[5];
    const float* Wq    = (const float*)d_in[6];
    const float* bq    = (const float*)d_in[7];
    const float* Wk    = (const float*)d_in[8];
    const float* bk    = (const float*)d_in[9];
    const float* Wv    = (const float*)d_in[10];
    const float* bv    = (const float*)d_in[11];
    const float* Wo    = (const float*)d_in[12];
    const float* bo    = (const float*)d_in[13];
    float* out = (float*)d_out;

    float *p_ln, *p_h1, *p_q, *p_k, *p_v, *p_attn;
    cudaGetSymbolAddress((void**)&p_ln,   g_ln);
    cudaGetSymbolAddress((void**)&p_h1,   g_h1);
    cudaGetSymbolAddress((void**)&p_q,    g_qb);
    cudaGetSymbolAddress((void**)&p_k,    g_kb);
    cudaGetSymbolAddress((void**)&p_v,    g_vb);
    cudaGetSymbolAddress((void**)&p_attn, g_attn);

    cudaFuncSetAttribute(attn_kernel, cudaFuncAttributeMaxDynamicSharedMemorySize,
                         (int)sizeof(AttnSmem));

    // 1) masked LayerNorm -> g_ln
    ln_kernel<<<dim3(T / 128, B), 128>>>(x, xm, gamma, beta);

    const dim3 ggrid(T / 64, C / 64, B);
    // 2) h1 = (Wp @ ln + bp) * m
    gemm_kernel<<<ggrid, 256>>>(Wp, bp, p_ln, xm, nullptr, p_h1);
    // 3-5) q,k,v = (W @ h1 + b) * m
    gemm_kernel<<<ggrid, 256>>>(Wq, bq, p_h1, xm, nullptr, p_q);
    gemm_kernel<<<ggrid, 256>>>(Wk, bk, p_h1, xm, nullptr, p_k);
    gemm_kernel<<<ggrid, 256>>>(Wv, bv, p_h1, xm, nullptr, p_v);
    // 6) flash attention -> g_attn
    attn_kernel<<<dim3(T / 64, B), 256, sizeof(AttnSmem)>>>(xm);
    // 7) out = (x + (Wo @ attn + bo) * m) * m
    gemm_kernel<<<ggrid, 256>>>(Wo, bo, p_attn, xm, x, out);
}

// round 17
// speedup vs baseline: 2.4240x; 2.4079x over previous
#include <cuda_runtime.h>
#include <math.h>
#include <stdint.h>

// Problem dims (fixed by the reference)
namespace {
constexpr int B = 4, C = 256, T = 4096;
constexpr float EPS = 1e-5f;
constexpr float NEG = -1e8f;
}

// ---------------------------------------------------------------------------
// Scratch buffers (static __device__ arrays — allocation-free per harness rules)
// ---------------------------------------------------------------------------
__device__ float g_ln  [(size_t)B * C * T];
__device__ float g_h1  [(size_t)B * C * T];
__device__ float g_qb  [(size_t)B * C * T];
__device__ float g_kb  [(size_t)B * C * T];
__device__ float g_vb  [(size_t)B * C * T];
__device__ float g_attn[(size_t)B * C * T];

// ---------------------------------------------------------------------------
// Kernel 1: masked LayerNorm over channel dim (unchanged)
// ---------------------------------------------------------------------------
__global__ void ln_kernel(const float* __restrict__ x,
                          const float* __restrict__ mask,
                          const float* __restrict__ gamma,
                          const float* __restrict__ beta) {
    const int b = blockIdx.y;
    const int t = blockIdx.x * blockDim.x + threadIdx.x;
    const float m = mask[(size_t)b * T + t];
    const float* xp = x + (size_t)b * C * T + t;

    float sum = 0.f, sq = 0.f;
#pragma unroll 8
    for (int c = 0; c < C; c++) {
        float v = __ldg(&xp[(size_t)c * T]) * m;
        sum += v;
        sq  += v * v;
    }
    const float mu  = sum * (1.0f / C);
    float var = sq * (1.0f / C) - mu * mu;
    var = fmaxf(var, 0.0f);
    const float rs = rsqrtf(var + EPS);

    float* op = g_ln + (size_t)b * C * T + t;
#pragma unroll 8
    for (int c = 0; c < C; c++) {
        float v = __ldg(&xp[(size_t)c * T]) * m;
        op[(size_t)c * T] = (v - mu) * rs * __ldg(&gamma[c]) + __ldg(&beta[c]);
    }
}

// ---------------------------------------------------------------------------
// Kernel 2: projection GEMM (unchanged — ~88% of FFMA roofline already)
// ---------------------------------------------------------------------------
__global__ __launch_bounds__(256) void gemm_kernel(
    const float* __restrict__ W, const float* __restrict__ bias,
    const float* __restrict__ in, const float* __restrict__ mask,
    const float* __restrict__ resid, float* __restrict__ out)
{
    __shared__ __align__(16) float As[16][68];
    __shared__ __align__(16) float Bs[16][68];

    const int b  = blockIdx.z;
    const int m0 = blockIdx.y * 64;
    const int n0 = blockIdx.x * 64;
    const int tid = threadIdx.x;
    const int tx = tid & 15, ty = tid >> 4;

    const float* inb = in + (size_t)b * C * T;
    float acc[4][4] = {};

    const int arow = tid >> 2;
    const int akc  = (tid & 3) * 4;
    const int brow = tid >> 4;
    const int bcol = (tid & 15) * 4;

    for (int k0 = 0; k0 < C; k0 += 16) {
        float4 a4 = *(const float4*)&W[(size_t)(m0 + arow) * C + k0 + akc];
        float4 b4 = *(const float4*)&inb[(size_t)(k0 + brow) * T + n0 + bcol];
        __syncthreads();
        As[akc + 0][arow] = a4.x;
        As[akc + 1][arow] = a4.y;
        As[akc + 2][arow] = a4.z;
        As[akc + 3][arow] = a4.w;
        *(float4*)&Bs[brow][bcol] = b4;
        __syncthreads();
#pragma unroll
        for (int k = 0; k < 16; k++) {
            float4 av4 = *(const float4*)&As[k][ty * 4];
            float4 bv4 = *(const float4*)&Bs[k][tx * 4];
            float av[4] = {av4.x, av4.y, av4.z, av4.w};
            float bv[4] = {bv4.x, bv4.y, bv4.z, bv4.w};
#pragma unroll
            for (int i = 0; i < 4; i++)
#pragma unroll
                for (int j = 0; j < 4; j++)
                    acc[i][j] = fmaf(av[i], bv[j], acc[i][j]);
        }
    }

    const int tglob = n0 + tx * 4;
    float4 mk4 = *(const float4*)&mask[(size_t)b * T + tglob];
    float mk[4] = {mk4.x, mk4.y, mk4.z, mk4.w};

#pragma unroll
    for (int i = 0; i < 4; i++) {
        const int o = m0 + ty * 4 + i;
        const float bo = __ldg(&bias[o]);
        const size_t base = ((size_t)b * C + o) * T + tglob;
        float vals[4];
#pragma unroll
        for (int j = 0; j < 4; j++) vals[j] = (acc[i][j] + bo) * mk[j];
        if (resid != nullptr) {
            float4 x4 = *(const float4*)&resid[base];
            float xr[4] = {x4.x, x4.y, x4.z, x4.w};
#pragma unroll
            for (int j = 0; j < 4; j++) vals[j] = (xr[j] + vals[j]) * mk[j];
        }
        *(float4*)&out[base] = make_float4(vals[0], vals[1], vals[2], vals[3]);
    }
}

// ---------------------------------------------------------------------------
// tf32 tensor-core helpers
// ---------------------------------------------------------------------------
__device__ __forceinline__ uint32_t f2tf(float x) {
    uint32_t r;
    asm("cvt.rna.tf32.f32 %0, %1;" : "=r"(r) : "f"(x));
    return r;
}

// D(16x8) += A(16x8 row) * B(8x8 col), tf32 in, fp32 accum
__device__ __forceinline__ void mma8(float d[4], const uint32_t a[4],
                                     const uint32_t bb[2]) {
    asm volatile(
        "mma.sync.aligned.m16n8k8.row.col.f32.tf32.tf32.f32 "
        "{%0,%1,%2,%3},{%4,%5,%6,%7},{%8,%9},{%0,%1,%2,%3};"
        : "+f"(d[0]), "+f"(d[1]), "+f"(d[2]), "+f"(d[3])
        : "r"(a[0]), "r"(a[1]), "r"(a[2]), "r"(a[3]), "r"(bb[0]), "r"(bb[1]));
}

// ---------------------------------------------------------------------------
// Kernel 3: flash attention on tf32 tensor cores.
// 64 queries/CTA, 128 threads (warp w owns q rows w*16..w*16+15 in QK phase,
// d rows {vch*128 + mm*64 + w*16} in PV phase). 32-key tiles.
// Smem strides: Qs 72, K/V 40, Ps 36 (mod-32 tuned for conflict-free frags).
// ---------------------------------------------------------------------------
struct AttnSmem {
    uint32_t Qs[256][72];   // tf32 Q, [c][q]        73728 B
    uint32_t KV[128 * 40];  // tf32 K/V chunk        20480 B
    uint32_t Ps[64][36];    // tf32 P, [q][s]         9216 B
    float bias_s[32];
    float alpha_s[64];
    float invl_s[64];
};                          // 104064 B -> 2 CTAs/SM

__global__ __launch_bounds__(128) void attn_kernel(const float* __restrict__ mask) {
    extern __shared__ __align__(16) char smraw[];
    AttnSmem* sm = reinterpret_cast<AttnSmem*>(smraw);

    const int b  = blockIdx.y;
    const int q0 = blockIdx.x * 64;
    const int tid  = threadIdx.x;
    const int lane = tid & 31, w = tid >> 5;
    const int grp = lane >> 2, t4 = lane & 3;
    const int q_lo = w * 16 + grp, q_hi = q_lo + 8;

    const float* Qb = g_qb + (size_t)b * C * T;
    const float* Kb = g_kb + (size_t)b * C * T;
    const float* Vb = g_vb + (size_t)b * C * T;
    const float* mb = mask + (size_t)b * T;

    // stage Q tile (tf32): Qs[c][q]
    for (int idx = tid; idx < 256 * 16; idx += 128) {
        const int c = idx >> 4, q4 = (idx & 15) << 2;
        float4 v = *(const float4*)&Qb[(size_t)c * T + q0 + q4];
        *(uint4*)&sm->Qs[c][q4] =
            make_uint4(f2tf(v.x), f2tf(v.y), f2tf(v.z), f2tf(v.w));
    }

    float O[4][8][4] = {};          // O^T frags: [md][jq][reg]
    float mi0 = -1e30f, mi1 = -1e30f, li0 = 0.f, li1 = 0.f;
    const float scale = 0.0625f;    // C^-0.5

    const int srow = tid >> 3;          // staging: 16 rows x 8 col-groups
    const int scol = (tid & 7) << 2;

    for (int s0 = 0; s0 < T; s0 += 32) {
        // ================= QK: S(16q x 32s) per warp =====================
        float S[4][4] = {};
#pragma unroll
        for (int cc = 0; cc < 2; cc++) {
            __syncthreads();            // KV buffer free
#pragma unroll
            for (int i = 0; i < 8; i++) {
                const int row = srow + i * 16;
                float4 v = *(const float4*)&Kb[(size_t)(cc * 128 + row) * T + s0 + scol];
                *(uint4*)&sm->KV[row * 40 + scol] =
                    make_uint4(f2tf(v.x), f2tf(v.y), f2tf(v.z), f2tf(v.w));
            }
            if (cc == 0 && tid < 32)
                sm->bias_s[tid] = (1.0f - __ldg(&mb[s0 + tid])) * NEG;
            __syncthreads();
#pragma unroll
            for (int kk = 0; kk < 16; kk++) {
                const int c = kk * 8;
                uint32_t a[4];
                a[0] = sm->Qs[cc * 128 + c + t4    ][q_lo];
                a[1] = sm->Qs[cc * 128 + c + t4    ][q_hi];
                a[2] = sm->Qs[cc * 128 + c + 4 + t4][q_lo];
                a[3] = sm->Qs[cc * 128 + c + 4 + t4][q_hi];
#pragma unroll
                for (int jt = 0; jt < 4; jt++) {
                    uint32_t bf[2];
                    bf[0] = sm->KV[(c + t4) * 40 + jt * 8 + grp];
                    bf[1] = sm->KV[(c + 4 + t4) * 40 + jt * 8 + grp];
                    mma8(S[jt], a, bf);
                }
            }
        }

        // ================= online softmax ================================
        // thread rows q_lo (regs 0,1), q_hi (regs 2,3); cols jt*8+2*t4+{0,1}
        float bb0[4], bb1[4];
#pragma unroll
        for (int jt = 0; jt < 4; jt++) {
            bb0[jt] = sm->bias_s[jt * 8 + 2 * t4];
            bb1[jt] = sm->bias_s[jt * 8 + 2 * t4 + 1];
        }
        float rm0 = -1e30f, rm1 = -1e30f;
#pragma unroll
        for (int jt = 0; jt < 4; jt++) {
            S[jt][0] = fmaf(S[jt][0], scale, bb0[jt]);
            S[jt][1] = fmaf(S[jt][1], scale, bb1[jt]);
            S[jt][2] = fmaf(S[jt][2], scale, bb0[jt]);
            S[jt][3] = fmaf(S[jt][3], scale, bb1[jt]);
            rm0 = fmaxf(rm0, fmaxf(S[jt][0], S[jt][1]));
            rm1 = fmaxf(rm1, fmaxf(S[jt][2], S[jt][3]));
        }
        rm0 = fmaxf(rm0, __shfl_xor_sync(0xffffffffu, rm0, 1));
        rm0 = fmaxf(rm0, __shfl_xor_sync(0xffffffffu, rm0, 2));
        rm1 = fmaxf(rm1, __shfl_xor_sync(0xffffffffu, rm1, 1));
        rm1 = fmaxf(rm1, __shfl_xor_sync(0xffffffffu, rm1, 2));

        const float mn0 = fmaxf(mi0, rm0), mn1 = fmaxf(mi1, rm1);
        const float al0 = __expf(mi0 - mn0), al1 = __expf(mi1 - mn1);
        float rs0 = 0.f, rs1 = 0.f;
#pragma unroll
        for (int jt = 0; jt < 4; jt++) {
            uint32_t p0 = f2tf(__expf(S[jt][0] - mn0));
            uint32_t p1 = f2tf(__expf(S[jt][1] - mn0));
            uint32_t p2 = f2tf(__expf(S[jt][2] - mn1));
            uint32_t p3 = f2tf(__expf(S[jt][3] - mn1));
            rs0 += __uint_as_float(p0) + __uint_as_float(p1); // tf32-rounded sums
            rs1 += __uint_as_float(p2) + __uint_as_float(p3);
            *(uint2*)&sm->Ps[q_lo][jt * 8 + 2 * t4] = make_uint2(p0, p1);
            *(uint2*)&sm->Ps[q_hi][jt * 8 + 2 * t4] = make_uint2(p2, p3);
        }
        rs0 += __shfl_xor_sync(0xffffffffu, rs0, 1);
        rs0 += __shfl_xor_sync(0xffffffffu, rs0, 2);
        rs1 += __shfl_xor_sync(0xffffffffu, rs1, 1);
        rs1 += __shfl_xor_sync(0xffffffffu, rs1, 2);
        li0 = li0 * al0 + rs0;  mi0 = mn0;
        li1 = li1 * al1 + rs1;  mi1 = mn1;
        if (t4 == 0) {
            sm->alpha_s[q_lo] = al0;
            sm->alpha_s[q_hi] = al1;
        }
        __syncthreads();   // Ps/alpha visible; all QK mmas done (KV free)

        // rescale O^T by per-q alpha (cols q = jq*8 + 2*t4 + {0,1})
        float avL[8], avH[8];
#pragma unroll
        for (int jq = 0; jq < 8; jq++) {
            float2 a2 = *(const float2*)&sm->alpha_s[jq * 8 + 2 * t4];
            avL[jq] = a2.x;  avH[jq] = a2.y;
        }
#pragma unroll
        for (int md = 0; md < 4; md++)
#pragma unroll
            for (int jq = 0; jq < 8; jq++) {
                O[md][jq][0] *= avL[jq];
                O[md][jq][1] *= avH[jq];
                O[md][jq][2] *= avL[jq];
                O[md][jq][3] *= avH[jq];
            }

        // ================= PV: O^T(d x q) += V(d x s) * P^T(s x q) =======
#pragma unroll
        for (int vch = 0; vch < 2; vch++) {
            if (vch) __syncthreads();
#pragma unroll
            for (int i = 0; i < 8; i++) {
                const int row = srow + i * 16;
                float4 v = *(const float4*)&Vb[(size_t)(vch * 128 + row) * T + s0 + scol];
                *(uint4*)&sm->KV[row * 40 + scol] =
                    make_uint4(f2tf(v.x), f2tf(v.y), f2tf(v.z), f2tf(v.w));
            }
            __syncthreads();
#pragma unroll
            for (int mm = 0; mm < 2; mm++) {
                const int md = vch * 2 + mm;
                const int dl = mm * 64 + w * 16;    // chunk-local d base
#pragma unroll
                for (int sk = 0; sk < 4; sk++) {
                    uint32_t a[4];
                    a[0] = sm->KV[(dl + grp    ) * 40 + sk * 8 + t4];
                    a[1] = sm->KV[(dl + grp + 8) * 40 + sk * 8 + t4];
                    a[2] = sm->KV[(dl + grp    ) * 40 + sk * 8 + t4 + 4];
                    a[3] = sm->KV[(dl + grp + 8) * 40 + sk * 8 + t4 + 4];
#pragma unroll
                    for (int jq = 0; jq < 8; jq++) {
                        uint32_t bp[2];
                        bp[0] = sm->Ps[jq * 8 + grp][sk * 8 + t4];
                        bp[1] = sm->Ps[jq * 8 + grp][sk * 8 + t4 + 4];
                        mma8(O[md][jq], a, bp);
                    }
                }
            }
        }
    }

    // ================= epilogue: scale by 1/l, store O^T[d][q] ===========
    if (t4 == 0) {
        sm->invl_s[q_lo] = 1.0f / li0;
        sm->invl_s[q_hi] = 1.0f / li1;
    }
    __syncthreads();
    float ivL[8], ivH[8];
#pragma unroll
    for (int jq = 0; jq < 8; jq++) {
        float2 v2 = *(const float2*)&sm->invl_s[jq * 8 + 2 * t4];
        ivL[jq] = v2.x;  ivH[jq] = v2.y;
    }
    float* Ob = g_attn + (size_t)b * C * T;
#pragma unroll
    for (int md = 0; md < 4; md++) {
        const int d0 = (md >> 1) * 128 + (md & 1) * 64 + w * 16;
        const int r0 = d0 + grp, r1 = d0 + grp + 8;
#pragma unroll
        for (int jq = 0; jq < 8; jq++) {
            const int q = q0 + jq * 8 + 2 * t4;
            *(float2*)&Ob[(size_t)r0 * T + q] =
                make_float2(O[md][jq][0] * ivL[jq], O[md][jq][1] * ivH[jq]);
            *(float2*)&Ob[(size_t)r1 * T + q] =
                make_float2(O[md][jq][2] * ivL[jq], O[md][jq][3] * ivH[jq]);
        }
    }
}

// ---------------------------------------------------------------------------
// Launcher: 7 kernel launches, graph-capturable, allocation-free.
// ---------------------------------------------------------------------------
extern "C" void kernel_launch(void* const* d_in, const int* in_sizes, int n_in,
                              void* d_out, int out_size) {
    const float* x     = (const float*)d_in[0];
    const float* xm    = (const float*)d_in[1];
    const float* gamma = (const float*)d_in[2];
    const float* beta  = (const float*)d_in[3];
    const float* Wp    = (const float*)d_in[4];
    const float* bp    = (const float*)d_in[5];
    const float* Wq    = (const float*)d_in[6];
    const float* bq    = (const float*)d_in[7];
    const float* Wk    = (const float*)d_in[8];
    const float* bk    = (const float*)d_in[9];
    const float* Wv    = (const float*)d_in[10];
    const float* bv    = (const float*)d_in[11];
    const float* Wo    = (const float*)d_in[12];
    const float* bo    = (const float*)d_in[13];
    float* out = (float*)d_out;

    float *p_ln, *p_h1, *p_q, *p_k, *p_v, *p_attn;
    cudaGetSymbolAddress((void**)&p_ln,   g_ln);
    cudaGetSymbolAddress((void**)&p_h1,   g_h1);
    cudaGetSymbolAddress((void**)&p_q,    g_qb);
    cudaGetSymbolAddress((void**)&p_k,    g_kb);
    cudaGetSymbolAddress((void**)&p_v,    g_vb);
    cudaGetSymbolAddress((void**)&p_attn, g_attn);

    cudaFuncSetAttribute(attn_kernel, cudaFuncAttributeMaxDynamicSharedMemorySize,
                         (int)sizeof(AttnSmem));

    ln_kernel<<<dim3(T / 128, B), 128>>>(x, xm, gamma, beta);

    const dim3 ggrid(T / 64, C / 64, B);
    gemm_kernel<<<ggrid, 256>>>(Wp, bp, p_ln, xm, nullptr, p_h1);
    gemm_kernel<<<ggrid, 256>>>(Wq, bq, p_h1, xm, nullptr, p_q);
    gemm_kernel<<<ggrid, 256>>>(Wk, bk, p_h1, xm, nullptr, p_k);
    gemm_kernel<<<ggrid, 256>>>(Wv, bv, p_h1, xm, nullptr, p_v);

    attn_kernel<<<dim3(T / 64, B), 128, sizeof(AttnSmem)>>>(xm);

    gemm_kernel<<<ggrid, 256>>>(Wo, bo, p_attn, xm, x, out);
}